// round 9
// baseline (speedup 1.0000x reference)
#include <cuda_runtime.h>
#include <cstdint>

// Problem constants (fixed by the dataset)
#define NTAB     8
#define BUCKETS  524288          // 2^19
#define BMASK    (BUCKETS - 1)
#define T_LEN    4096
#define HIST     128             // deepest lag
#define POS      64              // positions per group (kernel A)
#define THREADS  256
#define EXT      (POS + 120)     // 184: h8 needed at positions [t0-120, t0+POS)
#define MAXB     8               // max batch rows

// Gather kernel config: one 256B table row per thread, bulk-copied via TMA path
#define TB       128             // threads per gather block
#define RPB      128             // rows per gather block (32 KiB staged)

// Hash primes (low-32-bit arithmetic is exact for the %2^19 result)
#define P0 2654435761u
#define P1 2246822519u
#define P2 3266489917u
#define P3 2028178513u
#define P4 1220703125u
#define P5 1610612741u
#define P6 805306457u
#define P7 402653189u

// Scratch: bucket id per (row, t, table). 8*4096*8 ints = 1 MB.
__device__ int g_idx[MAXB * T_LEN * NTAB];

__device__ __forceinline__ unsigned smem_u32(const void* p) {
    unsigned a;
    asm("{ .reg .u64 t; cvta.to.shared.u64 t, %1; cvt.u32.u64 %0, t; }" : "=r"(a) : "l"(p));
    return a;
}

// ============================ Kernel A: indices ============================
__global__ void __launch_bounds__(THREADS)
index_kernel(const void* __restrict__ tokens_raw)
{
    __shared__ int      tok_s[HIST + POS];
    __shared__ unsigned A[EXT], Bf[EXT];
    __shared__ int      idx_s[POS * NTAB];
    __shared__ int      is32_s;

    const int*       tok32 = (const int*)tokens_raw;
    const long long* tok64 = (const long long*)tokens_raw;
    const int tid = threadIdx.x;

    // Inline dtype probe: int64 tokens (<2^31) have all-zero odd words.
    if (tid < 32) {
        unsigned any = __ballot_sync(0xFFFFFFFFu, tok32[2 * tid + 1] != 0);
        if (tid == 0) is32_s = (any != 0u);
    }

    const int groups_per_row = T_LEN / POS;       // 64
    const int row = blockIdx.x / groups_per_row;
    const int t0  = (blockIdx.x % groups_per_row) * POS;

    __syncthreads();
    const int is32 = is32_s;

    // Stage tokens t0-128 .. t0+POS-1 (zero-padded)
    for (int i = tid; i < HIST + POS; i += THREADS) {
        const int t = t0 - HIST + i;
        int v = 0;
        if (t >= 0) {
            const size_t k = (size_t)row * T_LEN + t;
            v = is32 ? tok32[k] : (int)tok64[k];
        }
        tok_s[i] = v;
    }
    __syncthreads();

    // h1,h2,h4,h8 chains. Position p = t0-120+i; lag-k token is tok_s[i+7-k].
    if (tid < EXT) {
        const int i = tid;
        const bool snap = (i >= 120);
        const int  tp   = i - 120;
        unsigned h = (unsigned)tok_s[i + 7] * P0;                    // window 1
        if (snap) idx_s[tp * NTAB + 0] = (int)(h & BMASK);
        h ^= (unsigned)tok_s[i + 6] * P1;                            // window 2
        if (snap) idx_s[tp * NTAB + 1] = (int)(h & BMASK);
        h ^= (unsigned)tok_s[i + 5] * P2;
        h ^= (unsigned)tok_s[i + 4] * P3;                            // window 4
        if (snap) idx_s[tp * NTAB + 2] = (int)(h & BMASK);
        h ^= (unsigned)tok_s[i + 3] * P4;
        h ^= (unsigned)tok_s[i + 2] * P5;
        h ^= (unsigned)tok_s[i + 1] * P6;
        h ^= (unsigned)tok_s[i + 0] * P7;                            // window 8
        A[i] = h;
        if (snap) idx_s[tp * NTAB + 3] = (int)(h & BMASK);
    }
    __syncthreads();

    // Log-doubling: h_{2w}(p) = h_w(p) ^ h_w(p-w).
    if (tid < EXT && tid >= 8) {                 // window 16
        unsigned h = A[tid] ^ A[tid - 8];
        Bf[tid] = h;
        if (tid >= 120) idx_s[(tid - 120) * NTAB + 4] = (int)(h & BMASK);
    }
    __syncthreads();
    if (tid < EXT && tid >= 24) {                // window 32
        unsigned h = Bf[tid] ^ Bf[tid - 16];
        A[tid] = h;
        if (tid >= 120) idx_s[(tid - 120) * NTAB + 5] = (int)(h & BMASK);
    }
    __syncthreads();
    if (tid < EXT && tid >= 56) {                // window 64
        unsigned h = A[tid] ^ A[tid - 32];
        Bf[tid] = h;
        if (tid >= 120) idx_s[(tid - 120) * NTAB + 6] = (int)(h & BMASK);
    }
    __syncthreads();
    if (tid >= 120 && tid < EXT) {               // window 128
        unsigned h = Bf[tid] ^ Bf[tid - 64];
        idx_s[(tid - 120) * NTAB + 7] = (int)(h & BMASK);
    }
    __syncthreads();

    // Write indices (coalesced, layout matches gather row order)
    const int base = (row * T_LEN + t0) * NTAB;
    #pragma unroll
    for (int i = tid; i < POS * NTAB; i += THREADS)
        g_idx[base + i] = idx_s[i];
}

// ================= Kernel B: TMA-path gather (bypasses L1tex MSHRs) ========
// Each thread bulk-copies one random 256B table row into SMEM (UBLKCP via the
// TMA engine, deep per-SM queue). One 32 KiB bulk store pushes the staged,
// already-contiguous output block to GMEM. No LDG/STG on the hot path.
__global__ void __launch_bounds__(TB)
gather_kernel(const char* __restrict__ tables, char* __restrict__ out)
{
    __shared__ __align__(256) char buf[RPB * 256];   // 32 KiB staging
    __shared__ unsigned long long mbar;

    const int tid = threadIdx.x;
    const int r0  = blockIdx.x * RPB;
    const unsigned mbar_a = smem_u32(&mbar);
    const unsigned buf_a  = smem_u32(buf);

    if (tid == 0) {
        asm volatile("mbarrier.init.shared.b64 [%0], 1;" :: "r"(mbar_a) : "memory");
    }
    __syncthreads();
    if (tid == 0) {
        asm volatile("mbarrier.arrive.expect_tx.shared.b64 _, [%0], %1;"
                     :: "r"(mbar_a), "r"(RPB * 256) : "memory");
    }
    __syncthreads();

    // Issue one 256B bulk gather per thread (row = (bt*T+t)*8 + tbl).
    {
        const int rw     = r0 + tid;
        const int tbl    = rw & 7;
        const int bucket = g_idx[rw];
        const char* src  = tables + (((size_t)tbl * BUCKETS + (size_t)bucket) << 8);
        const unsigned dst = buf_a + (unsigned)(tid << 8);
        asm volatile(
            "cp.async.bulk.shared::cluster.global.mbarrier::complete_tx::bytes "
            "[%0], [%1], %2, [%3];"
            :: "r"(dst), "l"(src), "r"(256), "r"(mbar_a) : "memory");
    }

    // Wait for all 32 KiB of gathered bytes.
    {
        unsigned done;
        asm volatile(
            "{\n\t.reg .pred p;\n\t"
            "mbarrier.try_wait.parity.acquire.cta.shared::cta.b64 p, [%1], 0;\n\t"
            "selp.b32 %0, 1, 0, p;\n\t}"
            : "=r"(done) : "r"(mbar_a) : "memory");
        if (!done) {
            asm volatile(
                "{\n\t.reg .pred P1;\n\t"
                "W%=:\n\t"
                "mbarrier.try_wait.parity.acquire.cta.shared::cta.b64 P1, [%0], 0, 0x989680;\n\t"
                "@P1 bra.uni D%=;\n\t"
                "bra.uni W%=;\n\t"
                "D%=:\n\t}"
                :: "r"(mbar_a) : "memory");
        }
    }
    __syncthreads();

    // Single 32 KiB contiguous bulk store SMEM -> GMEM.
    if (tid == 0) {
        asm volatile("fence.proxy.async.shared::cta;" ::: "memory");
        char* dstg = out + ((size_t)r0 << 8);
        asm volatile("cp.async.bulk.global.shared::cta.bulk_group [%0], [%1], %2;"
                     :: "l"(dstg), "r"(buf_a), "r"(RPB * 256) : "memory");
        asm volatile("cp.async.bulk.commit_group;" ::: "memory");
        asm volatile("cp.async.bulk.wait_group 0;" ::: "memory");
    }
    __syncthreads();   // block must not exit while the bulk store reads SMEM
}

extern "C" void kernel_launch(void* const* d_in, const int* in_sizes, int n_in,
                              void* d_out, int out_size)
{
    const void* tokens = d_in[0];                 // int64 OR int32 (B, T) — probed
    const char* tables = (const char*)d_in[1];    // fp32 (8, 524288, 64)
    char*       out    = (char*)d_out;            // fp32 (B, T, 512)

    const int rows  = in_sizes[0] / T_LEN;        // B = 8
    const int gridA = rows * (T_LEN / POS);       // 512
    const int total_rows = rows * T_LEN * NTAB;   // 262144 table rows
    const int gridB = total_rows / RPB;           // 2048

    index_kernel <<<gridA, THREADS>>>(tokens);
    gather_kernel<<<gridB, TB>>>(tables, out);
}

// round 10
// speedup vs baseline: 1.1616x; 1.1616x over previous
#include <cuda_runtime.h>
#include <cstdint>

// Problem constants (fixed by the dataset)
#define NTAB     8
#define BUCKETS  524288          // 2^19
#define BMASK    (BUCKETS - 1)
#define T_LEN    4096
#define HIST     128             // deepest lag
#define POS      128             // positions per group
#define SPLIT    8               // blocks per group (redundant hash, split gather)
#define THREADS  256
#define EXT      (POS + 120)     // 248: h8 needed at positions [t0-120, t0+POS)
#define F4_PB    (POS * NTAB * 16 / SPLIT)   // 2048 float4 units per block
#define U32B_PB  (F4_PB / 2)                 // 1024 32-byte units per block
#define BATCH    (U32B_PB / THREADS)         // 4 x 32B per thread

// Hash primes (low-32-bit arithmetic is exact for the %2^19 result)
#define P0 2654435761u
#define P1 2246822519u
#define P2 3266489917u
#define P3 2028178513u
#define P4 1220703125u
#define P5 1610612741u
#define P6 805306457u
#define P7 402653189u

__global__ void __launch_bounds__(THREADS, 5)
hash_tables_kernel(const void*   __restrict__ tokens_raw,
                   const float4* __restrict__ tables,   // [8, 524288, 64] fp32 as float4
                   float4*       __restrict__ out)      // [B, T, 512] fp32 as float4
{
    __shared__ int      tok_s[HIST + POS];   // 256 staged tokens (zero-padded)
    __shared__ unsigned A[EXT], Bf[EXT];     // ping-pong window-hash arrays
    __shared__ int      idx_s[POS * NTAB];   // bucket ids, [pos][window]
    __shared__ int      is32_s;

    const int*       tok32 = (const int*)tokens_raw;
    const long long* tok64 = (const long long*)tokens_raw;
    const int tid = threadIdx.x;

    // ---- Inline dtype probe: int64 tokens (<2^31) have all-zero odd words ----
    if (tid < 32) {
        unsigned any = __ballot_sync(0xFFFFFFFFu, tok32[2 * tid + 1] != 0);
        if (tid == 0) is32_s = (any != 0u);
    }

    const int groups_per_row = T_LEN / POS;                 // 32
    const int group = blockIdx.x / SPLIT;
    const int part  = blockIdx.x % SPLIT;
    const int row   = group / groups_per_row;
    const int t0    = (group % groups_per_row) * POS;

    __syncthreads();
    const int is32 = is32_s;

    // ---- Phase 1: stage tokens t0-128 .. t0+POS-1 (zero-padded) ----
    for (int i = tid; i < HIST + POS; i += THREADS) {
        const int t = t0 - HIST + i;
        int v = 0;
        if (t >= 0) {
            const size_t k = (size_t)row * T_LEN + t;
            v = is32 ? tok32[k] : (int)tok64[k];
        }
        tok_s[i] = v;
    }
    __syncthreads();

    // ---- Phase 2a: h1,h2,h4,h8 chains. Position p = t0-120+i; lag-k token
    // is tok_s[i+7-k]. Snapshots for gather positions (i >= 120). ----
    if (tid < EXT) {
        const int i = tid;
        const bool snap = (i >= 120);
        const int  tp   = i - 120;
        unsigned h = (unsigned)tok_s[i + 7] * P0;                    // window 1
        if (snap) idx_s[tp * NTAB + 0] = (int)(h & BMASK);
        h ^= (unsigned)tok_s[i + 6] * P1;                            // window 2
        if (snap) idx_s[tp * NTAB + 1] = (int)(h & BMASK);
        h ^= (unsigned)tok_s[i + 5] * P2;
        h ^= (unsigned)tok_s[i + 4] * P3;                            // window 4
        if (snap) idx_s[tp * NTAB + 2] = (int)(h & BMASK);
        h ^= (unsigned)tok_s[i + 3] * P4;
        h ^= (unsigned)tok_s[i + 2] * P5;
        h ^= (unsigned)tok_s[i + 1] * P6;
        h ^= (unsigned)tok_s[i + 0] * P7;                            // window 8
        A[i] = h;
        if (snap) idx_s[tp * NTAB + 3] = (int)(h & BMASK);
    }
    __syncthreads();

    // ---- Phase 2b: log-doubling. h_{2w}(p) = h_w(p) ^ h_w(p-w). ----
    if (tid < EXT && tid >= 8) {                 // window 16
        unsigned h = A[tid] ^ A[tid - 8];
        Bf[tid] = h;
        if (tid >= 120) idx_s[(tid - 120) * NTAB + 4] = (int)(h & BMASK);
    }
    __syncthreads();
    if (tid < EXT && tid >= 24) {                // window 32
        unsigned h = Bf[tid] ^ Bf[tid - 16];
        A[tid] = h;
        if (tid >= 120) idx_s[(tid - 120) * NTAB + 5] = (int)(h & BMASK);
    }
    __syncthreads();
    if (tid < EXT && tid >= 56) {                // window 64
        unsigned h = A[tid] ^ A[tid - 32];
        Bf[tid] = h;
        if (tid >= 120) idx_s[(tid - 120) * NTAB + 6] = (int)(h & BMASK);
    }
    __syncthreads();
    if (tid >= 120 && tid < EXT) {               // window 128
        unsigned h = Bf[tid] ^ Bf[tid - 64];
        idx_s[(tid - 120) * NTAB + 7] = (int)(h & BMASK);
    }
    __syncthreads();

    // ---- Phase 3: 256-bit gather (MLP=4x32B) + 256-bit streaming stores ----
    // 32B unit u covers float4 units {2u, 2u+1}. Table row rw = u>>3
    // (= pos*8 + tbl), 32B chunk c8 = u&7. This block covers
    // u in [part*U32B_PB, (part+1)*U32B_PB).
    const int u0 = part * U32B_PB;
    const size_t out32 = ((((size_t)row * T_LEN + t0) << 7) >> 1) + (size_t)u0;

    const char* src[BATCH];
    #pragma unroll
    for (int it = 0; it < BATCH; ++it) {
        const int u  = u0 + it * THREADS + tid;
        const int rw = u >> 3;                   // row = pos*8 + tbl
        const int c8 = u & 7;                    // 32B chunk in row
        const int tbl = rw & 7;
        const int bucket = idx_s[rw];
        src[it] = (const char*)tables
            + ((((size_t)tbl * BUCKETS + (size_t)bucket) << 8) | ((size_t)c8 << 5));
    }

    unsigned long long d0[BATCH], d1[BATCH], d2[BATCH], d3[BATCH];
    #pragma unroll
    for (int it = 0; it < BATCH; ++it) {
        asm volatile("ld.global.nc.L2::evict_last.v4.b64 {%0,%1,%2,%3}, [%4];"
                     : "=l"(d0[it]), "=l"(d1[it]), "=l"(d2[it]), "=l"(d3[it])
                     : "l"(src[it]));
    }
    #pragma unroll
    for (int it = 0; it < BATCH; ++it) {
        char* dst = (char*)out + ((out32 + (size_t)(it * THREADS + tid)) << 5);
        asm volatile("st.global.L2::evict_first.v4.b64 [%0], {%1,%2,%3,%4};"
                     :: "l"(dst), "l"(d0[it]), "l"(d1[it]), "l"(d2[it]), "l"(d3[it])
                     : "memory");
    }
}

extern "C" void kernel_launch(void* const* d_in, const int* in_sizes, int n_in,
                              void* d_out, int out_size)
{
    const void*   tokens = d_in[0];               // int64 OR int32 (B, T) — probed
    const float4* tables = (const float4*)d_in[1];// fp32 (8, 524288, 64)
    float4*       out    = (float4*)d_out;        // fp32 (B, T, 512)

    const int rows = in_sizes[0] / T_LEN;         // B = 8
    const int grid = rows * (T_LEN / POS) * SPLIT; // 2048 blocks
    hash_tables_kernel<<<grid, THREADS>>>(tokens, tables, out);
}

// round 11
// speedup vs baseline: 1.5333x; 1.3200x over previous
#include <cuda_runtime.h>
#include <cstdint>

// Problem constants (fixed by the dataset)
#define NTAB     8
#define BUCKETS  524288          // 2^19
#define BMASK    (BUCKETS - 1)
#define T_LEN    4096
#define HIST     128             // deepest lag
#define POS      64              // positions per group
#define SPLIT    2               // blocks per group (redundant hash, split gather)
#define THREADS  256
#define EXT      (POS + 120)     // 184: h8 needed at positions [t0-120, t0+POS)
#define F4_PB    (POS * NTAB * 16 / SPLIT)   // 4096 float4 units per block
#define U32B_PB  (F4_PB / 2)                 // 2048 32-byte units per block
#define BATCH    4                           // 4 x 32B per phase
#define PHASES   (U32B_PB / (THREADS * BATCH)) // 2 phases

// Hash primes (low-32-bit arithmetic is exact for the %2^19 result)
#define P0 2654435761u
#define P1 2246822519u
#define P2 3266489917u
#define P3 2028178513u
#define P4 1220703125u
#define P5 1610612741u
#define P6 805306457u
#define P7 402653189u

__global__ void __launch_bounds__(THREADS, 5)
hash_tables_kernel(const void*   __restrict__ tokens_raw,
                   const float4* __restrict__ tables,   // [8, 524288, 64] fp32 as float4
                   float4*       __restrict__ out)      // [B, T, 512] fp32 as float4
{
    __shared__ int      tok_s[HIST + POS];   // 192 staged tokens (zero-padded)
    __shared__ unsigned A[EXT], Bf[EXT];     // ping-pong window-hash arrays
    __shared__ int      idx_s[POS * NTAB];   // bucket ids, [pos][window]
    __shared__ int      is32_s;

    const int*       tok32 = (const int*)tokens_raw;
    const long long* tok64 = (const long long*)tokens_raw;
    const int tid = threadIdx.x;

    // ---- Inline dtype probe: int64 tokens (<2^31) have all-zero odd words ----
    if (tid < 32) {
        unsigned any = __ballot_sync(0xFFFFFFFFu, tok32[2 * tid + 1] != 0);
        if (tid == 0) is32_s = (any != 0u);
    }

    const int groups_per_row = T_LEN / POS;                 // 64
    const int group = blockIdx.x / SPLIT;
    const int part  = blockIdx.x % SPLIT;
    const int row   = group / groups_per_row;
    const int t0    = (group % groups_per_row) * POS;

    __syncthreads();
    const int is32 = is32_s;

    // ---- Phase 1: stage tokens t0-128 .. t0+POS-1 (zero-padded) ----
    for (int i = tid; i < HIST + POS; i += THREADS) {
        const int t = t0 - HIST + i;
        int v = 0;
        if (t >= 0) {
            const size_t k = (size_t)row * T_LEN + t;
            v = is32 ? tok32[k] : (int)tok64[k];
        }
        tok_s[i] = v;
    }
    __syncthreads();

    // ---- Phase 2a: h1,h2,h4,h8 chains. Position p = t0-120+i; lag-k token
    // is tok_s[i+7-k]. Snapshots for gather positions (i >= 120). ----
    if (tid < EXT) {
        const int i = tid;
        const bool snap = (i >= 120);
        const int  tp   = i - 120;
        unsigned h = (unsigned)tok_s[i + 7] * P0;                    // window 1
        if (snap) idx_s[tp * NTAB + 0] = (int)(h & BMASK);
        h ^= (unsigned)tok_s[i + 6] * P1;                            // window 2
        if (snap) idx_s[tp * NTAB + 1] = (int)(h & BMASK);
        h ^= (unsigned)tok_s[i + 5] * P2;
        h ^= (unsigned)tok_s[i + 4] * P3;                            // window 4
        if (snap) idx_s[tp * NTAB + 2] = (int)(h & BMASK);
        h ^= (unsigned)tok_s[i + 3] * P4;
        h ^= (unsigned)tok_s[i + 2] * P5;
        h ^= (unsigned)tok_s[i + 1] * P6;
        h ^= (unsigned)tok_s[i + 0] * P7;                            // window 8
        A[i] = h;
        if (snap) idx_s[tp * NTAB + 3] = (int)(h & BMASK);
    }
    __syncthreads();

    // ---- Phase 2b: log-doubling. h_{2w}(p) = h_w(p) ^ h_w(p-w). ----
    if (tid < EXT && tid >= 8) {                 // window 16
        unsigned h = A[tid] ^ A[tid - 8];
        Bf[tid] = h;
        if (tid >= 120) idx_s[(tid - 120) * NTAB + 4] = (int)(h & BMASK);
    }
    __syncthreads();
    if (tid < EXT && tid >= 24) {                // window 32
        unsigned h = Bf[tid] ^ Bf[tid - 16];
        A[tid] = h;
        if (tid >= 120) idx_s[(tid - 120) * NTAB + 5] = (int)(h & BMASK);
    }
    __syncthreads();
    if (tid < EXT && tid >= 56) {                // window 64
        unsigned h = A[tid] ^ A[tid - 32];
        Bf[tid] = h;
        if (tid >= 120) idx_s[(tid - 120) * NTAB + 6] = (int)(h & BMASK);
    }
    __syncthreads();
    if (tid >= 120 && tid < EXT) {               // window 128
        unsigned h = Bf[tid] ^ Bf[tid - 64];
        idx_s[(tid - 120) * NTAB + 7] = (int)(h & BMASK);
    }
    __syncthreads();

    // ---- Phase 3: 256-bit gathers (4x32B in flight per phase, 2 phases)
    // + 256-bit streaming stores. 32B unit u: table row rw = u>>3
    // (= pos*8 + tbl), 32B chunk c8 = u&7. Block covers
    // u in [part*U32B_PB, (part+1)*U32B_PB).
    const int u0 = part * U32B_PB;
    const size_t out32 = ((((size_t)row * T_LEN + t0) << 7) >> 1) + (size_t)u0;

    #pragma unroll
    for (int ph = 0; ph < PHASES; ++ph) {
        const int base = ph * THREADS * BATCH;

        const char* src[BATCH];
        #pragma unroll
        for (int it = 0; it < BATCH; ++it) {
            const int u  = u0 + base + it * THREADS + tid;
            const int rw = u >> 3;                   // row = pos*8 + tbl
            const int c8 = u & 7;                    // 32B chunk in row
            const int tbl = rw & 7;
            const int bucket = idx_s[rw];
            src[it] = (const char*)tables
                + ((((size_t)tbl * BUCKETS + (size_t)bucket) << 8) | ((size_t)c8 << 5));
        }

        unsigned long long d0[BATCH], d1[BATCH], d2[BATCH], d3[BATCH];
        #pragma unroll
        for (int it = 0; it < BATCH; ++it) {
            asm volatile("ld.global.nc.L2::evict_last.v4.b64 {%0,%1,%2,%3}, [%4];"
                         : "=l"(d0[it]), "=l"(d1[it]), "=l"(d2[it]), "=l"(d3[it])
                         : "l"(src[it]));
        }
        #pragma unroll
        for (int it = 0; it < BATCH; ++it) {
            char* dst = (char*)out
                + ((out32 + (size_t)(base + it * THREADS + tid)) << 5);
            asm volatile("st.global.L2::evict_first.v4.b64 [%0], {%1,%2,%3,%4};"
                         :: "l"(dst), "l"(d0[it]), "l"(d1[it]), "l"(d2[it]), "l"(d3[it])
                         : "memory");
        }
    }
}

extern "C" void kernel_launch(void* const* d_in, const int* in_sizes, int n_in,
                              void* d_out, int out_size)
{
    const void*   tokens = d_in[0];               // int64 OR int32 (B, T) — probed
    const float4* tables = (const float4*)d_in[1];// fp32 (8, 524288, 64)
    float4*       out    = (float4*)d_out;        // fp32 (B, T, 512)

    const int rows = in_sizes[0] / T_LEN;         // B = 8
    const int grid = rows * (T_LEN / POS) * SPLIT; // 1024 blocks
    hash_tables_kernel<<<grid, THREADS>>>(tokens, tables, out);
}

// round 12
// speedup vs baseline: 1.5359x; 1.0017x over previous
#include <cuda_runtime.h>
#include <cstdint>

// Problem constants (fixed by the dataset)
#define NTAB     8
#define BUCKETS  524288          // 2^19
#define BMASK    (BUCKETS - 1)
#define T_LEN    4096
#define HIST     128             // deepest lag
#define POS      64              // positions per block
#define THREADS  256
#define EXT      (POS + 120)     // 184: h8 needed at positions [t0-120, t0+POS)
#define F4_PB    (POS * NTAB * 16)           // 8192 float4 units per block
#define U32B_PB  (F4_PB / 2)                 // 4096 32-byte units per block
#define BATCH    4                           // 4 x 32B in flight per phase
#define PHASES   (U32B_PB / (THREADS * BATCH)) // 4 phases

// Hash primes (low-32-bit arithmetic is exact for the %2^19 result)
#define P0 2654435761u
#define P1 2246822519u
#define P2 3266489917u
#define P3 2028178513u
#define P4 1220703125u
#define P5 1610612741u
#define P6 805306457u
#define P7 402653189u

__global__ void __launch_bounds__(THREADS, 5)
hash_tables_kernel(const void*   __restrict__ tokens_raw,
                   const float4* __restrict__ tables,   // [8, 524288, 64] fp32 as float4
                   float4*       __restrict__ out)      // [B, T, 512] fp32 as float4
{
    __shared__ int      tok_s[HIST + POS];   // 192 staged tokens (zero-padded)
    __shared__ unsigned A[EXT], Bf[EXT];     // ping-pong window-hash arrays
    __shared__ int      idx_s[POS * NTAB];   // bucket ids, [pos][window]
    __shared__ int      is32_s;

    const int*       tok32 = (const int*)tokens_raw;
    const long long* tok64 = (const long long*)tokens_raw;
    const int tid = threadIdx.x;

    // ---- Inline dtype probe: int64 tokens (<2^31) have all-zero odd words ----
    if (tid < 32) {
        unsigned any = __ballot_sync(0xFFFFFFFFu, tok32[2 * tid + 1] != 0);
        if (tid == 0) is32_s = (any != 0u);
    }

    const int groups_per_row = T_LEN / POS;       // 64
    const int row = blockIdx.x / groups_per_row;
    const int t0  = (blockIdx.x % groups_per_row) * POS;

    __syncthreads();
    const int is32 = is32_s;

    // ---- Phase 1: stage tokens t0-128 .. t0+POS-1 (zero-padded) ----
    for (int i = tid; i < HIST + POS; i += THREADS) {
        const int t = t0 - HIST + i;
        int v = 0;
        if (t >= 0) {
            const size_t k = (size_t)row * T_LEN + t;
            v = is32 ? tok32[k] : (int)tok64[k];
        }
        tok_s[i] = v;
    }
    __syncthreads();

    // ---- Phase 2a: h1,h2,h4,h8 chains. Position p = t0-120+i; lag-k token
    // is tok_s[i+7-k]. Snapshots for gather positions (i >= 120). ----
    if (tid < EXT) {
        const int i = tid;
        const bool snap = (i >= 120);
        const int  tp   = i - 120;
        unsigned h = (unsigned)tok_s[i + 7] * P0;                    // window 1
        if (snap) idx_s[tp * NTAB + 0] = (int)(h & BMASK);
        h ^= (unsigned)tok_s[i + 6] * P1;                            // window 2
        if (snap) idx_s[tp * NTAB + 1] = (int)(h & BMASK);
        h ^= (unsigned)tok_s[i + 5] * P2;
        h ^= (unsigned)tok_s[i + 4] * P3;                            // window 4
        if (snap) idx_s[tp * NTAB + 2] = (int)(h & BMASK);
        h ^= (unsigned)tok_s[i + 3] * P4;
        h ^= (unsigned)tok_s[i + 2] * P5;
        h ^= (unsigned)tok_s[i + 1] * P6;
        h ^= (unsigned)tok_s[i + 0] * P7;                            // window 8
        A[i] = h;
        if (snap) idx_s[tp * NTAB + 3] = (int)(h & BMASK);
    }
    __syncthreads();

    // ---- Phase 2b: log-doubling. h_{2w}(p) = h_w(p) ^ h_w(p-w). ----
    if (tid < EXT && tid >= 8) {                 // window 16
        unsigned h = A[tid] ^ A[tid - 8];
        Bf[tid] = h;
        if (tid >= 120) idx_s[(tid - 120) * NTAB + 4] = (int)(h & BMASK);
    }
    __syncthreads();
    if (tid < EXT && tid >= 24) {                // window 32
        unsigned h = Bf[tid] ^ Bf[tid - 16];
        A[tid] = h;
        if (tid >= 120) idx_s[(tid - 120) * NTAB + 5] = (int)(h & BMASK);
    }
    __syncthreads();
    if (tid < EXT && tid >= 56) {                // window 64
        unsigned h = A[tid] ^ A[tid - 32];
        Bf[tid] = h;
        if (tid >= 120) idx_s[(tid - 120) * NTAB + 6] = (int)(h & BMASK);
    }
    __syncthreads();
    if (tid >= 120 && tid < EXT) {               // window 128
        unsigned h = Bf[tid] ^ Bf[tid - 64];
        idx_s[(tid - 120) * NTAB + 7] = (int)(h & BMASK);
    }
    __syncthreads();

    // ---- Phase 3: 256-bit gathers (4x32B in flight per phase, 4 phases)
    // + 256-bit streaming stores. 32B unit u: table row rw = u>>3
    // (= pos*8 + tbl), 32B chunk c8 = u&7. Block covers all 4096 units
    // of its 64-position group.
    const size_t out32 = (((size_t)row * T_LEN + t0) << 7) >> 1;   // 32B units

    #pragma unroll
    for (int ph = 0; ph < PHASES; ++ph) {
        const int base = ph * THREADS * BATCH;

        const char* src[BATCH];
        #pragma unroll
        for (int it = 0; it < BATCH; ++it) {
            const int u  = base + it * THREADS + tid;
            const int rw = u >> 3;                   // row = pos*8 + tbl
            const int c8 = u & 7;                    // 32B chunk in row
            const int tbl = rw & 7;
            const int bucket = idx_s[rw];
            src[it] = (const char*)tables
                + ((((size_t)tbl * BUCKETS + (size_t)bucket) << 8) | ((size_t)c8 << 5));
        }

        unsigned long long d0[BATCH], d1[BATCH], d2[BATCH], d3[BATCH];
        #pragma unroll
        for (int it = 0; it < BATCH; ++it) {
            asm volatile("ld.global.nc.L2::evict_last.v4.b64 {%0,%1,%2,%3}, [%4];"
                         : "=l"(d0[it]), "=l"(d1[it]), "=l"(d2[it]), "=l"(d3[it])
                         : "l"(src[it]));
        }
        #pragma unroll
        for (int it = 0; it < BATCH; ++it) {
            char* dst = (char*)out
                + ((out32 + (size_t)(base + it * THREADS + tid)) << 5);
            asm volatile("st.global.L2::evict_first.v4.b64 [%0], {%1,%2,%3,%4};"
                         :: "l"(dst), "l"(d0[it]), "l"(d1[it]), "l"(d2[it]), "l"(d3[it])
                         : "memory");
        }
    }
}

extern "C" void kernel_launch(void* const* d_in, const int* in_sizes, int n_in,
                              void* d_out, int out_size)
{
    const void*   tokens = d_in[0];               // int64 OR int32 (B, T) — probed
    const float4* tables = (const float4*)d_in[1];// fp32 (8, 524288, 64)
    float4*       out    = (float4*)d_out;        // fp32 (B, T, 512)

    const int rows = in_sizes[0] / T_LEN;         // B = 8
    const int grid = rows * (T_LEN / POS);        // 512 blocks
    hash_tables_kernel<<<grid, THREADS>>>(tokens, tables, out);
}